// round 1
// baseline (speedup 1.0000x reference)
#include <cuda_runtime.h>
#include <cuda_bf16.h>
#include <cstdint>

// Problem constants
#define Bb   8
#define Tt   4096
#define Dd   512
#define Pp   256
#define Mm   (Bb * Tt)     // 32768 rows
#define Kk   512
#define NPAD 896           // 769 logical columns padded to 7 tiles of 128

// ---------------- scratch (static device globals: no allocation) ----------------
__device__ __nv_bfloat16 g_WTh[NPAD * Kk];   // W concat, transposed [n][k], bf16 hi
__device__ __nv_bfloat16 g_WTl[NPAD * Kk];   // bf16 lo residual
__device__ float         g_bcat[NPAD];       // concatenated bias
__device__ float2        g_cs[(size_t)Mm * Pp];  // (cos, sin) per (bt, pair)
__device__ float         g_dec[Mm];              // sigmoid decay per (bt)

// ---------------- prep: build transposed split-bf16 weight + bias ----------------
__global__ void prep_kernel(const float* __restrict__ Wa, const float* __restrict__ ba,
                            const float* __restrict__ Wd, const float* __restrict__ bd,
                            const float* __restrict__ Wi, const float* __restrict__ bi) {
    int idx = blockIdx.x * 256 + threadIdx.x;
    if (idx < NPAD * Kk) {
        int n = idx >> 9;        // column in concatenated weight
        int k = idx & 511;       // input dim
        float w = 0.f;
        if (n < 256)        w = Wa[k * 256 + n];          // W_angle [512,256]
        else if (n < 768)   w = Wi[k * 512 + (n - 256)];  // W_input [512,512]
        else if (n == 768)  w = Wd[k];                    // W_decay [512,1]
        __nv_bfloat16 h = __float2bfloat16(w);
        __nv_bfloat16 l = __float2bfloat16(w - __bfloat162float(h));
        g_WTh[idx] = h;   // layout [n][k]
        g_WTl[idx] = l;
    }
    if (idx < NPAD) {
        float v = 0.f;
        if (idx < 256)       v = ba[idx];
        else if (idx < 768)  v = bi[idx - 256];
        else if (idx == 768) v = bd[0];
        g_bcat[idx] = v;
    }
}

// ---------------- fused projection GEMM (bf16 split mma.sync) ----------------
// C[32768, 896] = X @ Wcat; epilogue: cols 0..255 -> (cos,sin); 256..767 -> inj
// (written into d_out); 768 -> sigmoid decay; rest discarded.

__device__ __forceinline__ void emit_col(float* __restrict__ out, int bt, int n, float v) {
    v += g_bcat[n];
    if (n < 256) {
        float s, c;
        __sincosf(v, &s, &c);
        g_cs[(size_t)bt * 256 + n] = make_float2(c, s);
    } else if (n < 768) {
        out[(size_t)bt * 512 + (n - 256)] = v;
    } else if (n == 768) {
        g_dec[bt] = 1.0f / (1.0f + __expf(-v));
    }
}

#define MMA_BF16(C, A, B0, B1)                                                   \
    asm volatile("mma.sync.aligned.m16n8k16.row.col.f32.bf16.bf16.f32 "          \
                 "{%0,%1,%2,%3}, {%4,%5,%6,%7}, {%8,%9}, {%0,%1,%2,%3};\n"       \
                 : "+f"((C)[0]), "+f"((C)[1]), "+f"((C)[2]), "+f"((C)[3])        \
                 : "r"((A)[0]), "r"((A)[1]), "r"((A)[2]), "r"((A)[3]),           \
                   "r"(B0), "r"(B1))

__global__ __launch_bounds__(256, 2) void gemm_kernel(const float* __restrict__ X,
                                                      float* __restrict__ out) {
    // Smem tiles: A 128x32 (hi/lo), B 128(n) x 32(k) (hi/lo); row stride 40 bf16
    // (pad 8) -> conflict-free fragment loads.
    __shared__ __nv_bfloat16 Ah[128][40];
    __shared__ __nv_bfloat16 Al[128][40];
    __shared__ __nv_bfloat16 Bh[128][40];
    __shared__ __nv_bfloat16 Bl[128][40];

    const int tid  = threadIdx.x;
    const int m0   = blockIdx.y * 128;
    const int n0   = blockIdx.x * 128;
    const int warp = tid >> 5;
    const int lane = tid & 31;
    const int g    = lane >> 2;   // group id (0..7)
    const int q    = lane & 3;    // thread-in-group (0..3)
    const int wm   = (warp & 1) * 64;   // warp tile 64(m) x 32(n)
    const int wn   = (warp >> 1) * 32;

    float acc[4][4][4] = {};   // [mi][ni][c-regs]

    for (int kk = 0; kk < Kk; kk += 32) {
        __syncthreads();
        // ---- stage A: 128x32 fp32 -> split bf16 ----
        #pragma unroll
        for (int r = 0; r < 4; r++) {
            int f  = tid + r * 256;
            int m  = f >> 3;
            int k4 = (f & 7) << 2;
            float4 v = *reinterpret_cast<const float4*>(X + (size_t)(m0 + m) * Kk + kk + k4);
            float vv[4] = {v.x, v.y, v.z, v.w};
            #pragma unroll
            for (int j = 0; j < 4; j += 2) {
                __nv_bfloat16 h0 = __float2bfloat16(vv[j]);
                __nv_bfloat16 h1 = __float2bfloat16(vv[j + 1]);
                __nv_bfloat16 l0 = __float2bfloat16(vv[j]     - __bfloat162float(h0));
                __nv_bfloat16 l1 = __float2bfloat16(vv[j + 1] - __bfloat162float(h1));
                *reinterpret_cast<__nv_bfloat162*>(&Ah[m][k4 + j]) = __halves2bfloat162(h0, h1);
                *reinterpret_cast<__nv_bfloat162*>(&Al[m][k4 + j]) = __halves2bfloat162(l0, l1);
            }
        }
        // ---- stage B: 128(n) x 32(k) bf16 hi/lo straight copy ----
        #pragma unroll
        for (int r = 0; r < 2; r++) {
            int f  = tid + r * 256;
            int n  = f >> 2;
            int qq = (f & 3) << 3;
            size_t src = (size_t)(n0 + n) * Kk + kk + qq;
            *reinterpret_cast<uint4*>(&Bh[n][qq]) = *reinterpret_cast<const uint4*>(&g_WTh[src]);
            *reinterpret_cast<uint4*>(&Bl[n][qq]) = *reinterpret_cast<const uint4*>(&g_WTl[src]);
        }
        __syncthreads();

        // ---- compute: 2 k16 steps, 16 mma tiles, 3 splits ----
        #pragma unroll
        for (int ks = 0; ks < 32; ks += 16) {
            uint32_t bh[4][2], bl[4][2];
            #pragma unroll
            for (int ni = 0; ni < 4; ni++) {
                int n = wn + ni * 8 + g;
                bh[ni][0] = *reinterpret_cast<uint32_t*>(&Bh[n][ks + 2 * q]);
                bh[ni][1] = *reinterpret_cast<uint32_t*>(&Bh[n][ks + 2 * q + 8]);
                bl[ni][0] = *reinterpret_cast<uint32_t*>(&Bl[n][ks + 2 * q]);
                bl[ni][1] = *reinterpret_cast<uint32_t*>(&Bl[n][ks + 2 * q + 8]);
            }
            #pragma unroll
            for (int mi = 0; mi < 4; mi++) {
                int row = wm + mi * 16 + g;
                uint32_t ah[4], al[4];
                ah[0] = *reinterpret_cast<uint32_t*>(&Ah[row][ks + 2 * q]);
                ah[1] = *reinterpret_cast<uint32_t*>(&Ah[row + 8][ks + 2 * q]);
                ah[2] = *reinterpret_cast<uint32_t*>(&Ah[row][ks + 2 * q + 8]);
                ah[3] = *reinterpret_cast<uint32_t*>(&Ah[row + 8][ks + 2 * q + 8]);
                al[0] = *reinterpret_cast<uint32_t*>(&Al[row][ks + 2 * q]);
                al[1] = *reinterpret_cast<uint32_t*>(&Al[row + 8][ks + 2 * q]);
                al[2] = *reinterpret_cast<uint32_t*>(&Al[row][ks + 2 * q + 8]);
                al[3] = *reinterpret_cast<uint32_t*>(&Al[row + 8][ks + 2 * q + 8]);
                #pragma unroll
                for (int ni = 0; ni < 4; ni++) {
                    MMA_BF16(acc[mi][ni], ah, bh[ni][0], bh[ni][1]);  // xh*Wh
                    MMA_BF16(acc[mi][ni], al, bh[ni][0], bh[ni][1]);  // xl*Wh
                    MMA_BF16(acc[mi][ni], ah, bl[ni][0], bl[ni][1]);  // xh*Wl
                }
            }
        }
    }

    // ---- epilogue ----
    #pragma unroll
    for (int mi = 0; mi < 4; mi++) {
        #pragma unroll
        for (int ni = 0; ni < 4; ni++) {
            int row = m0 + wm + mi * 16 + g;
            int col = n0 + wn + ni * 8 + 2 * q;
            emit_col(out, row,     col,     acc[mi][ni][0]);
            emit_col(out, row,     col + 1, acc[mi][ni][1]);
            emit_col(out, row + 8, col,     acc[mi][ni][2]);
            emit_col(out, row + 8, col + 1, acc[mi][ni][3]);
        }
    }
}

// ---------------- sequential scan: h_t = d_t * R(a_t) h_{t-1} + u_t ----------------
// 2048 independent chains (b,p). 64 blocks x 32 threads; register pipeline PF=32
// so per-step time is bounded by max(12cy chain, DRAM_lat/32).
__global__ __launch_bounds__(32) void scan_kernel(float* __restrict__ out) {
    const int gid = blockIdx.x * 32 + threadIdx.x;   // 0..2047
    const int b   = gid >> 8;
    const int p   = gid & 255;

    const float2* csp = g_cs  + (size_t)b * Tt * Pp + p;   // stride 256 float2 per t
    const float*  dp  = g_dec + (size_t)b * Tt;
    float2*       op  = reinterpret_cast<float2*>(out) + (size_t)b * Tt * Pp + p;

    constexpr int PF = 32;
    float2 csr[PF], ur[PF];
    float  dr[PF];
    #pragma unroll
    for (int j = 0; j < PF; j++) {
        csr[j] = csp[(size_t)j * Pp];
        ur[j]  = op[(size_t)j * Pp];    // inj still stored in out
        dr[j]  = dp[j];
    }

    float h0 = 0.f, h1 = 0.f;
    for (int t0 = 0; t0 < Tt; t0 += PF) {
        #pragma unroll
        for (int j = 0; j < PF; j++) {
            float  c = csr[j].x, s = csr[j].y, d = dr[j];
            float2 u = ur[j];
            float he = c * h0 - s * h1;
            float ho = s * h0 + c * h1;
            h0 = fmaf(d, he, u.x);
            h1 = fmaf(d, ho, u.y);
            op[(size_t)(t0 + j) * Pp] = make_float2(h0, h1);
            int tn = t0 + j + PF;
            if (tn < Tt) {
                csr[j] = csp[(size_t)tn * Pp];
                ur[j]  = op[(size_t)tn * Pp];
                dr[j]  = dp[tn];
            }
        }
    }
}

// ---------------- launch ----------------
extern "C" void kernel_launch(void* const* d_in, const int* in_sizes, int n_in,
                              void* d_out, int out_size) {
    const float* x  = (const float*)d_in[0];
    const float* Wa = (const float*)d_in[1];
    const float* ba = (const float*)d_in[2];
    const float* Wd = (const float*)d_in[3];
    const float* bd = (const float*)d_in[4];
    const float* Wi = (const float*)d_in[5];
    const float* bi = (const float*)d_in[6];
    float* out = (float*)d_out;

    prep_kernel<<<(NPAD * Kk + 255) / 256, 256>>>(Wa, ba, Wd, bd, Wi, bi);

    dim3 grid(NPAD / 128, Mm / 128);   // (7, 256)
    gemm_kernel<<<grid, 256>>>(x, out);

    scan_kernel<<<64, 32>>>(out);
}

// round 3
// speedup vs baseline: 1.0704x; 1.0704x over previous
#include <cuda_runtime.h>
#include <cuda_bf16.h>
#include <cstdint>

// ---------------- problem constants ----------------
#define Bb 8
#define Tt 4096
#define Pp 256
#define Mm 32768
#define Kx 512            // original K
#define KP 1536           // extended K' : A'=[xh|xl|xh], B'=[Wh|Wh|Wl]
#define Nn 768            // angles 256 + inj 512
#define TILE_M 128
#define TILE_N 128
#define KC 64             // k-chunk (64 bf16 = 128B rows)
#define NCHUNK (KP / KC)  // 24
#define NSTAGES 4
#define A_BYTES (TILE_M * 128)          // 16384
#define B_BYTES (TILE_N * 128)          // 16384
#define STAGE_BYTES (A_BYTES + B_BYTES) // 32768
#define DYN_BYTES (NSTAGES * STAGE_BYTES)

// ---------------- device scratch (no allocation) ----------------
__device__ __nv_bfloat16 g_Ah[(size_t)Mm * Kx];
__device__ __nv_bfloat16 g_Al[(size_t)Mm * Kx];
__device__ __nv_bfloat16 g_Bc[(size_t)Nn * KP];
__device__ float         g_bcat[Nn];
__device__ float2        g_cs[(size_t)Mm * Pp];
__device__ float         g_dec[Mm];

// ---------------- helpers ----------------
__device__ __forceinline__ uint32_t smem_u32(const void* p) {
    uint32_t a;
    asm("{ .reg .u64 t; cvta.to.shared.u64 t, %1; cvt.u32.u64 %0, t; }" : "=r"(a) : "l"(p));
    return a;
}
#define SWZ(off) ((off) ^ (((off) >> 3) & 0x70))

#define CP_ASYNC16(dst, src) \
    asm volatile("cp.async.cg.shared.global [%0], [%1], 16;" :: "r"(dst), "l"(src))
#define CP_COMMIT() asm volatile("cp.async.commit_group;" ::: "memory")
#define CP_WAIT(n)  asm volatile("cp.async.wait_group %0;" :: "n"(n) : "memory")

__device__ __forceinline__ void ldsm_x4(uint32_t* r, uint32_t addr) {
    asm volatile("ldmatrix.sync.aligned.m8n8.x4.shared.b16 {%0,%1,%2,%3}, [%4];"
                 : "=r"(r[0]), "=r"(r[1]), "=r"(r[2]), "=r"(r[3]) : "r"(addr));
}

#define MMA_BF16(C, A, B0, B1)                                                   \
    asm volatile("mma.sync.aligned.m16n8k16.row.col.f32.bf16.bf16.f32 "          \
                 "{%0,%1,%2,%3}, {%4,%5,%6,%7}, {%8,%9}, {%0,%1,%2,%3};\n"       \
                 : "+f"((C)[0]), "+f"((C)[1]), "+f"((C)[2]), "+f"((C)[3])        \
                 : "r"((A)[0]), "r"((A)[1]), "r"((A)[2]), "r"((A)[3]),           \
                   "r"(B0), "r"(B1))

// ---------------- fast sincos (FMA pipe, no MUFU) ----------------
__device__ __forceinline__ void fsincos(float a, float& s, float& c) {
    float n = rintf(a * 0.6366197723675814f);          // 2/pi
    int q = (int)n;
    float r = fmaf(n, -1.5707963705062866f, a);        // -pi/2 hi
    r = fmaf(n, 4.3711388e-8f, r);                     // -pi/2 lo
    float r2 = r * r;
    float sp = r * fmaf(r2, fmaf(r2, fmaf(r2, -1.9841270e-4f, 8.3333338e-3f),
                                  -1.6666667e-1f), 1.0f);
    float cp = fmaf(r2, fmaf(r2, fmaf(r2, -1.3888889e-3f, 4.1666668e-2f), -0.5f), 1.0f);
    bool swap = q & 1;
    float ss = swap ? cp : sp;
    float cc = swap ? sp : cp;
    if (q & 2) ss = -ss;
    if ((q + 1) & 2) cc = -cc;
    s = ss; c = cc;
}

// ---------------- prep: B' = [Wh | Wh | Wl] transposed [n][kp], bias ----------------
__global__ void prep_kernel(const float* __restrict__ Wa, const float* __restrict__ ba,
                            const float* __restrict__ Wi, const float* __restrict__ bi) {
    int n  = blockIdx.y;
    int kp = blockIdx.x * 256 + threadIdx.x;   // 0..1535
    int r  = kp >> 9;
    int k  = kp & 511;
    float w = (n < 256) ? Wa[k * 256 + n] : Wi[k * 512 + (n - 256)];
    __nv_bfloat16 h = __float2bfloat16(w);
    g_Bc[(size_t)n * KP + kp] = (r < 2) ? h : __float2bfloat16(w - __bfloat162float(h));
    if (blockIdx.x == 0 && threadIdx.x == 0)
        g_bcat[n] = (n < 256) ? ba[n] : bi[n - 256];
}

// ---------------- conv: X -> bf16 hi/lo (once), fused decay GEMV ----------------
__global__ __launch_bounds__(256) void conv_kernel(const float* __restrict__ X,
                                                   const float* __restrict__ Wd,
                                                   const float* __restrict__ bd) {
    int wid = threadIdx.x >> 5, lane = threadIdx.x & 31;
    size_t row = (size_t)blockIdx.x * 8 + wid;
    const float4* xp = (const float4*)(X + row * Kx);
    const float4* wp = (const float4*)Wd;
    float acc = 0.f;
    #pragma unroll
    for (int j = 0; j < 4; j++) {
        int idx = j * 32 + lane;
        float4 v = xp[idx];
        float4 w = wp[idx];
        acc = fmaf(v.x, w.x, fmaf(v.y, w.y, fmaf(v.z, w.z, fmaf(v.w, w.w, acc))));
        __nv_bfloat162 H0 = __floats2bfloat162_rn(v.x, v.y);
        __nv_bfloat162 H1 = __floats2bfloat162_rn(v.z, v.w);
        __nv_bfloat162 L0 = __floats2bfloat162_rn(v.x - __low2float(H0), v.y - __high2float(H0));
        __nv_bfloat162 L1 = __floats2bfloat162_rn(v.z - __low2float(H1), v.w - __high2float(H1));
        uint2 hp, lp;
        hp.x = *(uint32_t*)&H0; hp.y = *(uint32_t*)&H1;
        lp.x = *(uint32_t*)&L0; lp.y = *(uint32_t*)&L1;
        *(uint2*)(g_Ah + row * Kx + idx * 4) = hp;
        *(uint2*)(g_Al + row * Kx + idx * 4) = lp;
    }
    #pragma unroll
    for (int o = 16; o; o >>= 1) acc += __shfl_xor_sync(0xffffffffu, acc, o);
    if (!lane) g_dec[row] = 1.f / (1.f + __expf(-(acc + bd[0])));
}

// ---------------- GEMM: mma.sync bf16, cp.async 4-stage pipe, ldmatrix ----------------
// C[32768, 768] = A'[32768,1536] @ B'[768,1536]^T ; fused bias + sincos epilogue.
__global__ __launch_bounds__(256) void gemm_kernel(float* __restrict__ out) {
    extern __shared__ char dyn[];
    const uint32_t dbase = smem_u32(dyn);
    __shared__ float s_bias[TILE_N];

    const int tid  = threadIdx.x;
    const int warp = tid >> 5;
    const int lane = tid & 31;
    const int g    = lane >> 2;
    const int q    = lane & 3;
    const int m0   = blockIdx.y * TILE_M;
    const int n0   = blockIdx.x * TILE_N;
    const int wm   = (warp & 1) * 64;      // 2x4 warp grid, each 64m x 32n
    const int wn   = (warp >> 1) * 32;

    if (tid < TILE_N) s_bias[tid] = g_bcat[n0 + tid];

    // per-thread cp.async coordinates (4 x 16B per tile)
    const int arow = tid >> 3;             // 0..31 base row (stride 32)
    const int aj   = tid & 7;              // 16B column

    // issue one chunk's loads
    auto issue = [&](int c) {
        const int s = c & (NSTAGES - 1);
        const __nv_bfloat16* Ap = ((c >> 3) == 1) ? g_Al : g_Ah;  // split select
        const int xk0 = (c & 7) * KC;
        uint32_t stA = dbase + s * STAGE_BYTES;
        uint32_t stB = stA + A_BYTES;
        #pragma unroll
        for (int i = 0; i < 4; i++) {
            int row = arow + i * 32;
            uint32_t off = SWZ((uint32_t)(row * 128 + aj * 16));
            CP_ASYNC16(stA + off, (const char*)(Ap + (size_t)(m0 + row) * Kx + xk0) + aj * 16);
            CP_ASYNC16(stB + off, (const char*)(g_Bc + (size_t)(n0 + row) * KP + c * KC) + aj * 16);
        }
    };

    float acc[4][4][4] = {};   // [mi][ni][c]

    // prologue: fill 3 stages
    issue(0); CP_COMMIT();
    issue(1); CP_COMMIT();
    issue(2); CP_COMMIT();

    // ldmatrix lane addressing
    const int a_r  = lane & 15;            // row within 16
    const int a_kh = (lane >> 4) * 16;     // k-half byte offset (8 elems)
    const int b_n  = lane & 15;            // n row within 16
    const int b_kh = (lane >> 4) * 16;

    for (int c = 0; c < NCHUNK; ++c) {
        const int s = c & (NSTAGES - 1);
        CP_WAIT(2);
        __syncthreads();
        if (c + 3 < NCHUNK) issue(c + 3);
        CP_COMMIT();

        const uint32_t stA = dbase + s * STAGE_BYTES;
        const uint32_t stB = stA + A_BYTES;

        #pragma unroll
        for (int ks = 0; ks < 4; ks++) {
            // B frags: 2 x ldmatrix.x4, each covers n16 x k16 -> b[ni] pairs
            uint32_t bf[4][2];
            #pragma unroll
            for (int h = 0; h < 2; h++) {
                uint32_t r[4];
                uint32_t off = (uint32_t)((wn + h * 16 + b_n) * 128 + ks * 32 + b_kh);
                ldsm_x4(r, stB + SWZ(off));
                bf[h * 2 + 0][0] = r[0]; bf[h * 2 + 0][1] = r[2];
                bf[h * 2 + 1][0] = r[1]; bf[h * 2 + 1][1] = r[3];
            }
            #pragma unroll
            for (int mi = 0; mi < 4; mi++) {
                uint32_t af[4];
                uint32_t off = (uint32_t)((wm + mi * 16 + a_r) * 128 + ks * 32 + a_kh);
                ldsm_x4(af, stA + SWZ(off));
                #pragma unroll
                for (int ni = 0; ni < 4; ni++)
                    MMA_BF16(acc[mi][ni], af, bf[ni][0], bf[ni][1]);
            }
        }
    }

    // ---- epilogue: bias + (sincos -> g_cs) or (inj -> out) ----
    const bool is_angle = (n0 < 256);
    #pragma unroll
    for (int mi = 0; mi < 4; mi++) {
        const int r0 = m0 + wm + mi * 16 + g;
        #pragma unroll
        for (int ni = 0; ni < 4; ni++) {
            const int col = wn + ni * 8 + 2 * q;        // within tile, even
            const float b0 = s_bias[col], b1 = s_bias[col + 1];
            float v0 = acc[mi][ni][0] + b0;
            float v1 = acc[mi][ni][1] + b1;
            float v2 = acc[mi][ni][2] + b0;
            float v3 = acc[mi][ni][3] + b1;
            if (is_angle) {
                const int pc = n0 + col;
                float s0, c0, s1, c1, s2, c2, s3, c3;
                fsincos(v0, s0, c0); fsincos(v1, s1, c1);
                fsincos(v2, s2, c2); fsincos(v3, s3, c3);
                *(float4*)(&g_cs[(size_t)r0 * 256 + pc])       = make_float4(c0, s0, c1, s1);
                *(float4*)(&g_cs[(size_t)(r0 + 8) * 256 + pc]) = make_float4(c2, s2, c3, s3);
            } else {
                const int e = n0 - 256 + col;
                *(float2*)(out + (size_t)r0 * 512 + e)       = make_float2(v0, v1);
                *(float2*)(out + (size_t)(r0 + 8) * 512 + e) = make_float2(v2, v3);
            }
        }
    }
}

// ---------------- sequential scan: h_t = d_t * R(a_t) h_{t-1} + u_t ----------------
__global__ __launch_bounds__(32) void scan_kernel(float* __restrict__ out) {
    const int gid = blockIdx.x * 32 + threadIdx.x;   // 0..2047
    const int b   = gid >> 8;
    const int p   = gid & 255;

    const float2* csp = g_cs  + (size_t)b * Tt * Pp + p;
    const float*  dp  = g_dec + (size_t)b * Tt;
    float2*       op  = reinterpret_cast<float2*>(out) + (size_t)b * Tt * Pp + p;

    constexpr int PF = 32;
    float2 csr[PF], ur[PF];
    float  dr[PF];
    #pragma unroll
    for (int j = 0; j < PF; j++) {
        csr[j] = csp[(size_t)j * Pp];
        ur[j]  = op[(size_t)j * Pp];
        dr[j]  = dp[j];
    }

    float h0 = 0.f, h1 = 0.f;
    for (int t0 = 0; t0 < Tt; t0 += PF) {
        #pragma unroll
        for (int j = 0; j < PF; j++) {
            float  c = csr[j].x, s = csr[j].y, d = dr[j];
            float2 u = ur[j];
            float he = c * h0 - s * h1;
            float ho = s * h0 + c * h1;
            h0 = fmaf(d, he, u.x);
            h1 = fmaf(d, ho, u.y);
            op[(size_t)(t0 + j) * Pp] = make_float2(h0, h1);
            int tn = t0 + j + PF;
            if (tn < Tt) {
                csr[j] = csp[(size_t)tn * Pp];
                ur[j]  = op[(size_t)tn * Pp];
                dr[j]  = dp[tn];
            }
        }
    }
}

// ---------------- launch ----------------
extern "C" void kernel_launch(void* const* d_in, const int* in_sizes, int n_in,
                              void* d_out, int out_size) {
    const float* x  = (const float*)d_in[0];
    const float* Wa = (const float*)d_in[1];
    const float* ba = (const float*)d_in[2];
    const float* Wd = (const float*)d_in[3];
    const float* bd = (const float*)d_in[4];
    const float* Wi = (const float*)d_in[5];
    const float* bi = (const float*)d_in[6];
    float* out = (float*)d_out;

    cudaFuncSetAttribute(gemm_kernel, cudaFuncAttributeMaxDynamicSharedMemorySize, DYN_BYTES);

    prep_kernel<<<dim3(KP / 256, Nn), 256>>>(Wa, ba, Wi, bi);
    conv_kernel<<<Mm / 8, 256>>>(x, Wd, bd);
    gemm_kernel<<<dim3(Nn / TILE_N, Mm / TILE_M), 256, DYN_BYTES>>>(out);
    scan_kernel<<<64, 32>>>(out);
}

// round 4
// speedup vs baseline: 1.4403x; 1.3456x over previous
#include <cuda_runtime.h>
#include <cuda_bf16.h>
#include <cstdint>

// ---------------- problem constants ----------------
#define Bb 8
#define Tt 4096
#define Pp 256
#define Mm 32768
#define Kx 512            // original K
#define KP 1536           // extended K' : A'=[xh|xl|xh], B'=[Wh|Wh|Wl]
#define Nn 768            // angles 256 + inj 512
#define TILE_M 128
#define TILE_N 128
#define KC 64             // k-chunk (64 bf16 = 128B rows)
#define NCHUNK (KP / KC)  // 24
#define NSTAGES 4
#define A_BYTES (TILE_M * 128)          // 16384
#define B_BYTES (TILE_N * 128)          // 16384
#define STAGE_BYTES (A_BYTES + B_BYTES) // 32768
#define DYN_BYTES (NSTAGES * STAGE_BYTES)

// scan chunking
#define SCHUNK 32                 // timesteps per chunk
#define NCH (Tt / SCHUNK)         // 128 chunks per sequence

// ---------------- device scratch (no allocation) ----------------
__device__ __nv_bfloat16 g_Ah[(size_t)Mm * Kx];
__device__ __nv_bfloat16 g_Al[(size_t)Mm * Kx];
__device__ __nv_bfloat16 g_Bc[(size_t)Nn * KP];
__device__ float         g_bcat[Nn];
__device__ float2        g_cs[(size_t)Mm * Pp];
__device__ float         g_dec[Mm];
__device__ float4        g_agg[(size_t)Bb * NCH * Pp];     // (Zr,Zi,Ur,Ui)
__device__ float2        g_hst[(size_t)Bb * NCH * Pp];     // chunk-start state

// ---------------- helpers ----------------
__device__ __forceinline__ uint32_t smem_u32(const void* p) {
    uint32_t a;
    asm("{ .reg .u64 t; cvta.to.shared.u64 t, %1; cvt.u32.u64 %0, t; }" : "=r"(a) : "l"(p));
    return a;
}
#define SWZ(off) ((off) ^ (((off) >> 3) & 0x70))

#define CP_ASYNC16(dst, src) \
    asm volatile("cp.async.cg.shared.global [%0], [%1], 16;" :: "r"(dst), "l"(src))
#define CP_COMMIT() asm volatile("cp.async.commit_group;" ::: "memory")
#define CP_WAIT(n)  asm volatile("cp.async.wait_group %0;" :: "n"(n) : "memory")

__device__ __forceinline__ void ldsm_x4(uint32_t* r, uint32_t addr) {
    asm volatile("ldmatrix.sync.aligned.m8n8.x4.shared.b16 {%0,%1,%2,%3}, [%4];"
                 : "=r"(r[0]), "=r"(r[1]), "=r"(r[2]), "=r"(r[3]) : "r"(addr));
}

#define MMA_BF16(C, A, B0, B1)                                                   \
    asm volatile("mma.sync.aligned.m16n8k16.row.col.f32.bf16.bf16.f32 "          \
                 "{%0,%1,%2,%3}, {%4,%5,%6,%7}, {%8,%9}, {%0,%1,%2,%3};\n"       \
                 : "+f"((C)[0]), "+f"((C)[1]), "+f"((C)[2]), "+f"((C)[3])        \
                 : "r"((A)[0]), "r"((A)[1]), "r"((A)[2]), "r"((A)[3]),           \
                   "r"(B0), "r"(B1))

// ---------------- fast sincos (FMA pipe, no MUFU) ----------------
__device__ __forceinline__ void fsincos(float a, float& s, float& c) {
    float n = rintf(a * 0.6366197723675814f);          // 2/pi
    int q = (int)n;
    float r = fmaf(n, -1.5707963705062866f, a);        // -pi/2 hi
    r = fmaf(n, 4.3711388e-8f, r);                     // -pi/2 lo
    float r2 = r * r;
    float sp = r * fmaf(r2, fmaf(r2, fmaf(r2, -1.9841270e-4f, 8.3333338e-3f),
                                  -1.6666667e-1f), 1.0f);
    float cp = fmaf(r2, fmaf(r2, fmaf(r2, -1.3888889e-3f, 4.1666668e-2f), -0.5f), 1.0f);
    bool swap = q & 1;
    float ss = swap ? cp : sp;
    float cc = swap ? sp : cp;
    if (q & 2) ss = -ss;
    if ((q + 1) & 2) cc = -cc;
    s = ss; c = cc;
}

// ---------------- prep: B' = [Wh | Wh | Wl] transposed [n][kp], bias ----------------
__global__ void prep_kernel(const float* __restrict__ Wa, const float* __restrict__ ba,
                            const float* __restrict__ Wi, const float* __restrict__ bi) {
    int n  = blockIdx.y;
    int kp = blockIdx.x * 256 + threadIdx.x;   // 0..1535
    int r  = kp >> 9;
    int k  = kp & 511;
    float w = (n < 256) ? Wa[k * 256 + n] : Wi[k * 512 + (n - 256)];
    __nv_bfloat16 h = __float2bfloat16(w);
    g_Bc[(size_t)n * KP + kp] = (r < 2) ? h : __float2bfloat16(w - __bfloat162float(h));
    if (blockIdx.x == 0 && threadIdx.x == 0)
        g_bcat[n] = (n < 256) ? ba[n] : bi[n - 256];
}

// ---------------- conv: X -> bf16 hi/lo (once), fused decay GEMV ----------------
__global__ __launch_bounds__(256) void conv_kernel(const float* __restrict__ X,
                                                   const float* __restrict__ Wd,
                                                   const float* __restrict__ bd) {
    int wid = threadIdx.x >> 5, lane = threadIdx.x & 31;
    size_t row = (size_t)blockIdx.x * 8 + wid;
    const float4* xp = (const float4*)(X + row * Kx);
    const float4* wp = (const float4*)Wd;
    float acc = 0.f;
    #pragma unroll
    for (int j = 0; j < 4; j++) {
        int idx = j * 32 + lane;
        float4 v = xp[idx];
        float4 w = wp[idx];
        acc = fmaf(v.x, w.x, fmaf(v.y, w.y, fmaf(v.z, w.z, fmaf(v.w, w.w, acc))));
        __nv_bfloat162 H0 = __floats2bfloat162_rn(v.x, v.y);
        __nv_bfloat162 H1 = __floats2bfloat162_rn(v.z, v.w);
        __nv_bfloat162 L0 = __floats2bfloat162_rn(v.x - __low2float(H0), v.y - __high2float(H0));
        __nv_bfloat162 L1 = __floats2bfloat162_rn(v.z - __low2float(H1), v.w - __high2float(H1));
        uint2 hp, lp;
        hp.x = *(uint32_t*)&H0; hp.y = *(uint32_t*)&H1;
        lp.x = *(uint32_t*)&L0; lp.y = *(uint32_t*)&L1;
        *(uint2*)(g_Ah + row * Kx + idx * 4) = hp;
        *(uint2*)(g_Al + row * Kx + idx * 4) = lp;
    }
    #pragma unroll
    for (int o = 16; o; o >>= 1) acc += __shfl_xor_sync(0xffffffffu, acc, o);
    if (!lane) g_dec[row] = 1.f / (1.f + __expf(-(acc + bd[0])));
}

// ---------------- GEMM: mma.sync bf16, cp.async 4-stage pipe, ldmatrix ----------------
__global__ __launch_bounds__(256) void gemm_kernel(float* __restrict__ out) {
    extern __shared__ char dyn[];
    const uint32_t dbase = smem_u32(dyn);
    __shared__ float s_bias[TILE_N];

    const int tid  = threadIdx.x;
    const int warp = tid >> 5;
    const int lane = tid & 31;
    const int g    = lane >> 2;
    const int q    = lane & 3;
    const int m0   = blockIdx.y * TILE_M;
    const int n0   = blockIdx.x * TILE_N;
    const int wm   = (warp & 1) * 64;
    const int wn   = (warp >> 1) * 32;

    if (tid < TILE_N) s_bias[tid] = g_bcat[n0 + tid];

    const int arow = tid >> 3;
    const int aj   = tid & 7;

    auto issue = [&](int c) {
        const int s = c & (NSTAGES - 1);
        const __nv_bfloat16* Ap = ((c >> 3) == 1) ? g_Al : g_Ah;
        const int xk0 = (c & 7) * KC;
        uint32_t stA = dbase + s * STAGE_BYTES;
        uint32_t stB = stA + A_BYTES;
        #pragma unroll
        for (int i = 0; i < 4; i++) {
            int row = arow + i * 32;
            uint32_t off = SWZ((uint32_t)(row * 128 + aj * 16));
            CP_ASYNC16(stA + off, (const char*)(Ap + (size_t)(m0 + row) * Kx + xk0) + aj * 16);
            CP_ASYNC16(stB + off, (const char*)(g_Bc + (size_t)(n0 + row) * KP + c * KC) + aj * 16);
        }
    };

    float acc[4][4][4] = {};

    issue(0); CP_COMMIT();
    issue(1); CP_COMMIT();
    issue(2); CP_COMMIT();

    const int a_r  = lane & 15;
    const int a_kh = (lane >> 4) * 16;
    const int b_n  = lane & 15;
    const int b_kh = (lane >> 4) * 16;

    for (int c = 0; c < NCHUNK; ++c) {
        const int s = c & (NSTAGES - 1);
        CP_WAIT(2);
        __syncthreads();
        if (c + 3 < NCHUNK) issue(c + 3);
        CP_COMMIT();

        const uint32_t stA = dbase + s * STAGE_BYTES;
        const uint32_t stB = stA + A_BYTES;

        #pragma unroll
        for (int ks = 0; ks < 4; ks++) {
            uint32_t bf[4][2];
            #pragma unroll
            for (int h = 0; h < 2; h++) {
                uint32_t r[4];
                uint32_t off = (uint32_t)((wn + h * 16 + b_n) * 128 + ks * 32 + b_kh);
                ldsm_x4(r, stB + SWZ(off));
                bf[h * 2 + 0][0] = r[0]; bf[h * 2 + 0][1] = r[2];
                bf[h * 2 + 1][0] = r[1]; bf[h * 2 + 1][1] = r[3];
            }
            #pragma unroll
            for (int mi = 0; mi < 4; mi++) {
                uint32_t af[4];
                uint32_t off = (uint32_t)((wm + mi * 16 + a_r) * 128 + ks * 32 + a_kh);
                ldsm_x4(af, stA + SWZ(off));
                #pragma unroll
                for (int ni = 0; ni < 4; ni++)
                    MMA_BF16(acc[mi][ni], af, bf[ni][0], bf[ni][1]);
            }
        }
    }

    const bool is_angle = (n0 < 256);
    #pragma unroll
    for (int mi = 0; mi < 4; mi++) {
        const int r0 = m0 + wm + mi * 16 + g;
        #pragma unroll
        for (int ni = 0; ni < 4; ni++) {
            const int col = wn + ni * 8 + 2 * q;
            const float b0 = s_bias[col], b1 = s_bias[col + 1];
            float v0 = acc[mi][ni][0] + b0;
            float v1 = acc[mi][ni][1] + b1;
            float v2 = acc[mi][ni][2] + b0;
            float v3 = acc[mi][ni][3] + b1;
            if (is_angle) {
                const int pc = n0 + col;
                float s0, c0, s1, c1, s2, c2, s3, c3;
                fsincos(v0, s0, c0); fsincos(v1, s1, c1);
                fsincos(v2, s2, c2); fsincos(v3, s3, c3);
                *(float4*)(&g_cs[(size_t)r0 * 256 + pc])       = make_float4(c0, s0, c1, s1);
                *(float4*)(&g_cs[(size_t)(r0 + 8) * 256 + pc]) = make_float4(c2, s2, c3, s3);
            } else {
                const int e = n0 - 256 + col;
                *(float2*)(out + (size_t)r0 * 512 + e)       = make_float2(v0, v1);
                *(float2*)(out + (size_t)(r0 + 8) * 512 + e) = make_float2(v2, v3);
            }
        }
    }
}

// ---------------- parallel scan: h_t = z_t h_{t-1} + u_t, z complex ----------------
// Pass A: per (b,chunk,p) local aggregate (Z = prod z, U = local h from 0)
__global__ __launch_bounds__(256) void scanA_kernel(const float* __restrict__ out) {
    const int p     = threadIdx.x;
    const int chunk = blockIdx.x;
    const int b     = blockIdx.y;
    const int t0    = chunk * SCHUNK;

    __shared__ float sd[SCHUNK];
    if (p < SCHUNK) sd[p] = g_dec[b * Tt + t0 + p];
    __syncthreads();

    const float2* csp = g_cs + ((size_t)b * Tt + t0) * Pp + p;
    const float2* up  = (const float2*)out + ((size_t)b * Tt + t0) * Pp + p;

    float Zr = 1.f, Zi = 0.f, hr = 0.f, hi = 0.f;
    #pragma unroll 4
    for (int j = 0; j < SCHUNK; j++) {
        float2 cs = csp[(size_t)j * Pp];
        float2 u  = up[(size_t)j * Pp];
        float d = sd[j];
        float zr = d * cs.x, zi = d * cs.y;
        float nhr = fmaf(zr, hr, fmaf(-zi, hi, u.x));
        float nhi = fmaf(zr, hi, fmaf( zi, hr, u.y));
        hr = nhr; hi = nhi;
        float nZr = zr * Zr - zi * Zi;
        float nZi = fmaf(zr, Zi, zi * Zr);
        Zr = nZr; Zi = nZi;
    }
    g_agg[((size_t)b * NCH + chunk) * Pp + p] = make_float4(Zr, Zi, hr, hi);
}

// Pass B: scan chunk aggregates -> exclusive chunk-start states
__global__ __launch_bounds__(256) void scanB_kernel() {
    const int gid = blockIdx.x * 256 + threadIdx.x;   // 0..2047
    const int b = gid >> 8, p = gid & 255;
    float hr = 0.f, hi = 0.f;
    for (int c = 0; c < NCH; c++) {
        const size_t idx = ((size_t)b * NCH + c) * Pp + p;
        float4 a = g_agg[idx];
        g_hst[idx] = make_float2(hr, hi);
        float nhr = fmaf(a.x, hr, fmaf(-a.y, hi, a.z));
        float nhi = fmaf(a.x, hi, fmaf( a.y, hr, a.w));
        hr = nhr; hi = nhi;
    }
}

// Pass C: replay local recurrence seeded with chunk-start state, write out
__global__ __launch_bounds__(256) void scanC_kernel(float* __restrict__ out) {
    const int p     = threadIdx.x;
    const int chunk = blockIdx.x;
    const int b     = blockIdx.y;
    const int t0    = chunk * SCHUNK;

    __shared__ float sd[SCHUNK];
    if (p < SCHUNK) sd[p] = g_dec[b * Tt + t0 + p];
    __syncthreads();

    const float2* csp = g_cs + ((size_t)b * Tt + t0) * Pp + p;
    float2*       op  = (float2*)out + ((size_t)b * Tt + t0) * Pp + p;

    float2 h0 = g_hst[((size_t)b * NCH + chunk) * Pp + p];
    float hr = h0.x, hi = h0.y;
    #pragma unroll 4
    for (int j = 0; j < SCHUNK; j++) {
        float2 cs = csp[(size_t)j * Pp];
        float2 u  = op[(size_t)j * Pp];
        float d = sd[j];
        float zr = d * cs.x, zi = d * cs.y;
        float nhr = fmaf(zr, hr, fmaf(-zi, hi, u.x));
        float nhi = fmaf(zr, hi, fmaf( zi, hr, u.y));
        hr = nhr; hi = nhi;
        op[(size_t)j * Pp] = make_float2(hr, hi);
    }
}

// ---------------- launch ----------------
extern "C" void kernel_launch(void* const* d_in, const int* in_sizes, int n_in,
                              void* d_out, int out_size) {
    const float* x  = (const float*)d_in[0];
    const float* Wa = (const float*)d_in[1];
    const float* ba = (const float*)d_in[2];
    const float* Wd = (const float*)d_in[3];
    const float* bd = (const float*)d_in[4];
    const float* Wi = (const float*)d_in[5];
    const float* bi = (const float*)d_in[6];
    float* out = (float*)d_out;

    cudaFuncSetAttribute(gemm_kernel, cudaFuncAttributeMaxDynamicSharedMemorySize, DYN_BYTES);

    prep_kernel<<<dim3(KP / 256, Nn), 256>>>(Wa, ba, Wi, bi);
    conv_kernel<<<Mm / 8, 256>>>(x, Wd, bd);
    gemm_kernel<<<dim3(Nn / TILE_N, Mm / TILE_M), 256, DYN_BYTES>>>(out);
    scanA_kernel<<<dim3(NCH, Bb), 256>>>(out);
    scanB_kernel<<<Bb, 256>>>();
    scanC_kernel<<<dim3(NCH, Bb), 256>>>(out);
}

// round 5
// speedup vs baseline: 1.9995x; 1.3883x over previous
#include <cuda_runtime.h>
#include <cuda_fp16.h>
#include <cstdint>

// ---------------- problem constants ----------------
#define Bb 8
#define Tt 4096
#define Pp 256
#define Mm 32768
#define Kx 512            // original K
#define KP 1024           // extended K' : A'=[xh|xl] (fp16), B reused for both halves
#define Nn 768            // angles 256 + inj 512
#define TILE_M 128
#define TILE_N 128
#define KC 64             // k-chunk (64 fp16 = 128B rows)
#define NCHUNK (KP / KC)  // 16
#define NSTAGES 3
#define A_BYTES (TILE_M * 128)          // 16384
#define B_BYTES (TILE_N * 128)          // 16384
#define STAGE_BYTES (A_BYTES + B_BYTES) // 32768
#define DYN_BYTES (NSTAGES * STAGE_BYTES)   // 98304 -> 2 CTAs/SM

// scan chunking
#define SCHUNK 32
#define NCH (Tt / SCHUNK)         // 128

// ---------------- device scratch (no allocation) ----------------
__device__ __half  g_Ah[(size_t)Mm * Kx];
__device__ __half  g_Al[(size_t)Mm * Kx];
__device__ __half  g_Bh[(size_t)Nn * Kx];
__device__ float   g_bcat[Nn];
__device__ float2  g_cs[(size_t)Mm * Pp];
__device__ float   g_dec[Mm];
__device__ float4  g_agg[(size_t)Bb * NCH * Pp];
__device__ float2  g_hst[(size_t)Bb * NCH * Pp];

// ---------------- helpers ----------------
__device__ __forceinline__ uint32_t smem_u32(const void* p) {
    uint32_t a;
    asm("{ .reg .u64 t; cvta.to.shared.u64 t, %1; cvt.u32.u64 %0, t; }" : "=r"(a) : "l"(p));
    return a;
}
#define SWZ(off) ((off) ^ (((off) >> 3) & 0x70))

#define CP_ASYNC16(dst, src) \
    asm volatile("cp.async.cg.shared.global [%0], [%1], 16;" :: "r"(dst), "l"(src))
#define CP_COMMIT() asm volatile("cp.async.commit_group;" ::: "memory")
#define CP_WAIT(n)  asm volatile("cp.async.wait_group %0;" :: "n"(n) : "memory")

__device__ __forceinline__ void ldsm_x4(uint32_t* r, uint32_t addr) {
    asm volatile("ldmatrix.sync.aligned.m8n8.x4.shared.b16 {%0,%1,%2,%3}, [%4];"
                 : "=r"(r[0]), "=r"(r[1]), "=r"(r[2]), "=r"(r[3]) : "r"(addr));
}

#define MMA_F16(C, A, B0, B1)                                                    \
    asm volatile("mma.sync.aligned.m16n8k16.row.col.f32.f16.f16.f32 "            \
                 "{%0,%1,%2,%3}, {%4,%5,%6,%7}, {%8,%9}, {%0,%1,%2,%3};\n"       \
                 : "+f"((C)[0]), "+f"((C)[1]), "+f"((C)[2]), "+f"((C)[3])        \
                 : "r"((A)[0]), "r"((A)[1]), "r"((A)[2]), "r"((A)[3]),           \
                   "r"(B0), "r"(B1))

// ---------------- fast sincos (FMA pipe, no MUFU) ----------------
__device__ __forceinline__ void fsincos(float a, float& s, float& c) {
    float n = rintf(a * 0.6366197723675814f);
    int q = (int)n;
    float r = fmaf(n, -1.5707963705062866f, a);
    r = fmaf(n, 4.3711388e-8f, r);
    float r2 = r * r;
    float sp = r * fmaf(r2, fmaf(r2, fmaf(r2, -1.9841270e-4f, 8.3333338e-3f),
                                  -1.6666667e-1f), 1.0f);
    float cp = fmaf(r2, fmaf(r2, fmaf(r2, -1.3888889e-3f, 4.1666668e-2f), -0.5f), 1.0f);
    bool swap = q & 1;
    float ss = swap ? cp : sp;
    float cc = swap ? sp : cp;
    if (q & 2) ss = -ss;
    if ((q + 1) & 2) cc = -cc;
    s = ss; c = cc;
}

// ---------------- prep: Wh fp16 transposed [n][k], bias ----------------
__global__ void prep_kernel(const float* __restrict__ Wa, const float* __restrict__ ba,
                            const float* __restrict__ Wi, const float* __restrict__ bi) {
    int n = blockIdx.y;
    int k = blockIdx.x * 256 + threadIdx.x;   // 0..511
    float w = (n < 256) ? Wa[k * 256 + n] : Wi[k * 512 + (n - 256)];
    g_Bh[(size_t)n * Kx + k] = __float2half_rn(w);
    if (blockIdx.x == 0 && threadIdx.x == 0)
        g_bcat[n] = (n < 256) ? ba[n] : bi[n - 256];
}

// ---------------- conv: X -> fp16 hi/lo split, fused decay GEMV ----------------
__global__ __launch_bounds__(256) void conv_kernel(const float* __restrict__ X,
                                                   const float* __restrict__ Wd,
                                                   const float* __restrict__ bd) {
    int wid = threadIdx.x >> 5, lane = threadIdx.x & 31;
    size_t row = (size_t)blockIdx.x * 8 + wid;
    const float4* xp = (const float4*)(X + row * Kx);
    const float4* wp = (const float4*)Wd;
    float acc = 0.f;
    #pragma unroll
    for (int j = 0; j < 4; j++) {
        int idx = j * 32 + lane;
        float4 v = xp[idx];
        float4 w = wp[idx];
        acc = fmaf(v.x, w.x, fmaf(v.y, w.y, fmaf(v.z, w.z, fmaf(v.w, w.w, acc))));
        __half hx = __float2half_rn(v.x), hy = __float2half_rn(v.y);
        __half hz = __float2half_rn(v.z), hw = __float2half_rn(v.w);
        __half lx = __float2half_rn(v.x - __half2float(hx));
        __half ly = __float2half_rn(v.y - __half2float(hy));
        __half lz = __float2half_rn(v.z - __half2float(hz));
        __half lw = __float2half_rn(v.w - __half2float(hw));
        __half2 H0 = __halves2half2(hx, hy), H1 = __halves2half2(hz, hw);
        __half2 L0 = __halves2half2(lx, ly), L1 = __halves2half2(lz, lw);
        uint2 hp, lp;
        hp.x = *(uint32_t*)&H0; hp.y = *(uint32_t*)&H1;
        lp.x = *(uint32_t*)&L0; lp.y = *(uint32_t*)&L1;
        *(uint2*)(g_Ah + row * Kx + idx * 4) = hp;
        *(uint2*)(g_Al + row * Kx + idx * 4) = lp;
    }
    #pragma unroll
    for (int o = 16; o; o >>= 1) acc += __shfl_xor_sync(0xffffffffu, acc, o);
    if (!lane) g_dec[row] = 1.f / (1.f + __expf(-(acc + bd[0])));
}

// ---------------- GEMM: fp16 mma.sync, 3-stage cp.async, 2 CTAs/SM ----------------
// C[32768,768] = (xh+xl)[32768,512] @ Wh[768,512]^T ; fused bias+sincos epilogue.
__global__ __launch_bounds__(256, 2) void gemm_kernel(float* __restrict__ out) {
    extern __shared__ char dyn[];
    const uint32_t dbase = smem_u32(dyn);
    __shared__ float s_bias[TILE_N];

    const int tid  = threadIdx.x;
    const int warp = tid >> 5;
    const int lane = tid & 31;
    const int g    = lane >> 2;
    const int q    = lane & 3;
    const int m0   = blockIdx.y * TILE_M;
    const int n0   = blockIdx.x * TILE_N;
    const int wm   = (warp & 1) * 64;
    const int wn   = (warp >> 1) * 32;

    if (tid < TILE_N) s_bias[tid] = g_bcat[n0 + tid];

    const int arow = tid >> 3;
    const int aj   = tid & 7;

    auto issue = [&](int c) {
        const int s = c % NSTAGES;
        const __half* Ap = (c < 8) ? g_Ah : g_Al;   // hi half then lo half
        const int xk0 = (c & 7) * KC;
        uint32_t stA = dbase + s * STAGE_BYTES;
        uint32_t stB = stA + A_BYTES;
        #pragma unroll
        for (int i = 0; i < 4; i++) {
            int row = arow + i * 32;
            uint32_t off = SWZ((uint32_t)(row * 128 + aj * 16));
            CP_ASYNC16(stA + off, (const char*)(Ap + (size_t)(m0 + row) * Kx + xk0) + aj * 16);
            CP_ASYNC16(stB + off, (const char*)(g_Bh + (size_t)(n0 + row) * Kx + xk0) + aj * 16);
        }
    };

    float acc[4][4][4] = {};

    issue(0); CP_COMMIT();
    issue(1); CP_COMMIT();

    const int a_r  = lane & 15;
    const int a_kh = (lane >> 4) * 16;
    const int b_n  = lane & 15;
    const int b_kh = (lane >> 4) * 16;

    for (int c = 0; c < NCHUNK; ++c) {
        const int s = c % NSTAGES;
        CP_WAIT(1);
        __syncthreads();
        if (c + 2 < NCHUNK) issue(c + 2);
        CP_COMMIT();

        const uint32_t stA = dbase + s * STAGE_BYTES;
        const uint32_t stB = stA + A_BYTES;

        #pragma unroll
        for (int ks = 0; ks < 4; ks++) {
            uint32_t bf[4][2];
            #pragma unroll
            for (int h = 0; h < 2; h++) {
                uint32_t r[4];
                uint32_t off = (uint32_t)((wn + h * 16 + b_n) * 128 + ks * 32 + b_kh);
                ldsm_x4(r, stB + SWZ(off));
                bf[h * 2 + 0][0] = r[0]; bf[h * 2 + 0][1] = r[2];
                bf[h * 2 + 1][0] = r[1]; bf[h * 2 + 1][1] = r[3];
            }
            #pragma unroll
            for (int mi = 0; mi < 4; mi++) {
                uint32_t af[4];
                uint32_t off = (uint32_t)((wm + mi * 16 + a_r) * 128 + ks * 32 + a_kh);
                ldsm_x4(af, stA + SWZ(off));
                #pragma unroll
                for (int ni = 0; ni < 4; ni++)
                    MMA_F16(acc[mi][ni], af, bf[ni][0], bf[ni][1]);
            }
        }
    }

    const bool is_angle = (n0 < 256);
    #pragma unroll
    for (int mi = 0; mi < 4; mi++) {
        const int r0 = m0 + wm + mi * 16 + g;
        #pragma unroll
        for (int ni = 0; ni < 4; ni++) {
            const int col = wn + ni * 8 + 2 * q;
            const float b0 = s_bias[col], b1 = s_bias[col + 1];
            float v0 = acc[mi][ni][0] + b0;
            float v1 = acc[mi][ni][1] + b1;
            float v2 = acc[mi][ni][2] + b0;
            float v3 = acc[mi][ni][3] + b1;
            if (is_angle) {
                const int pc = n0 + col;
                float s0, c0, s1, c1, s2, c2, s3, c3;
                fsincos(v0, s0, c0); fsincos(v1, s1, c1);
                fsincos(v2, s2, c2); fsincos(v3, s3, c3);
                *(float4*)(&g_cs[(size_t)r0 * 256 + pc])       = make_float4(c0, s0, c1, s1);
                *(float4*)(&g_cs[(size_t)(r0 + 8) * 256 + pc]) = make_float4(c2, s2, c3, s3);
            } else {
                const int e = n0 - 256 + col;
                *(float2*)(out + (size_t)r0 * 512 + e)       = make_float2(v0, v1);
                *(float2*)(out + (size_t)(r0 + 8) * 512 + e) = make_float2(v2, v3);
            }
        }
    }
}

// ---------------- parallel scan (3 passes) ----------------
__global__ __launch_bounds__(256) void scanA_kernel(const float* __restrict__ out) {
    const int p     = threadIdx.x;
    const int chunk = blockIdx.x;
    const int b     = blockIdx.y;
    const int t0    = chunk * SCHUNK;

    __shared__ float sd[SCHUNK];
    if (p < SCHUNK) sd[p] = g_dec[b * Tt + t0 + p];
    __syncthreads();

    const float2* csp = g_cs + ((size_t)b * Tt + t0) * Pp + p;
    const float2* up  = (const float2*)out + ((size_t)b * Tt + t0) * Pp + p;

    float Zr = 1.f, Zi = 0.f, hr = 0.f, hi = 0.f;
    #pragma unroll 4
    for (int j = 0; j < SCHUNK; j++) {
        float2 cs = csp[(size_t)j * Pp];
        float2 u  = up[(size_t)j * Pp];
        float d = sd[j];
        float zr = d * cs.x, zi = d * cs.y;
        float nhr = fmaf(zr, hr, fmaf(-zi, hi, u.x));
        float nhi = fmaf(zr, hi, fmaf( zi, hr, u.y));
        hr = nhr; hi = nhi;
        float nZr = zr * Zr - zi * Zi;
        float nZi = fmaf(zr, Zi, zi * Zr);
        Zr = nZr; Zi = nZi;
    }
    g_agg[((size_t)b * NCH + chunk) * Pp + p] = make_float4(Zr, Zi, hr, hi);
}

__global__ __launch_bounds__(256) void scanB_kernel() {
    const int gid = blockIdx.x * 256 + threadIdx.x;
    const int b = gid >> 8, p = gid & 255;
    float hr = 0.f, hi = 0.f;
    for (int c = 0; c < NCH; c++) {
        const size_t idx = ((size_t)b * NCH + c) * Pp + p;
        float4 a = g_agg[idx];
        g_hst[idx] = make_float2(hr, hi);
        float nhr = fmaf(a.x, hr, fmaf(-a.y, hi, a.z));
        float nhi = fmaf(a.x, hi, fmaf( a.y, hr, a.w));
        hr = nhr; hi = nhi;
    }
}

__global__ __launch_bounds__(256) void scanC_kernel(float* __restrict__ out) {
    const int p     = threadIdx.x;
    const int chunk = blockIdx.x;
    const int b     = blockIdx.y;
    const int t0    = chunk * SCHUNK;

    __shared__ float sd[SCHUNK];
    if (p < SCHUNK) sd[p] = g_dec[b * Tt + t0 + p];
    __syncthreads();

    const float2* csp = g_cs + ((size_t)b * Tt + t0) * Pp + p;
    float2*       op  = (float2*)out + ((size_t)b * Tt + t0) * Pp + p;

    float2 h0 = g_hst[((size_t)b * NCH + chunk) * Pp + p];
    float hr = h0.x, hi = h0.y;
    #pragma unroll 4
    for (int j = 0; j < SCHUNK; j++) {
        float2 cs = csp[(size_t)j * Pp];
        float2 u  = op[(size_t)j * Pp];
        float d = sd[j];
        float zr = d * cs.x, zi = d * cs.y;
        float nhr = fmaf(zr, hr, fmaf(-zi, hi, u.x));
        float nhi = fmaf(zr, hi, fmaf( zi, hr, u.y));
        hr = nhr; hi = nhi;
        op[(size_t)j * Pp] = make_float2(hr, hi);
    }
}

// ---------------- launch ----------------
extern "C" void kernel_launch(void* const* d_in, const int* in_sizes, int n_in,
                              void* d_out, int out_size) {
    const float* x  = (const float*)d_in[0];
    const float* Wa = (const float*)d_in[1];
    const float* ba = (const float*)d_in[2];
    const float* Wd = (const float*)d_in[3];
    const float* bd = (const float*)d_in[4];
    const float* Wi = (const float*)d_in[5];
    const float* bi = (const float*)d_in[6];
    float* out = (float*)d_out;

    cudaFuncSetAttribute(gemm_kernel, cudaFuncAttributeMaxDynamicSharedMemorySize, DYN_BYTES);

    prep_kernel<<<dim3(Kx / 256, Nn), 256>>>(Wa, ba, Wi, bi);
    conv_kernel<<<Mm / 8, 256>>>(x, Wd, bd);
    gemm_kernel<<<dim3(Nn / TILE_N, Mm / TILE_M), 256, DYN_BYTES>>>(out);
    scanA_kernel<<<dim3(NCH, Bb), 256>>>(out);
    scanB_kernel<<<Bb, 256>>>();
    scanC_kernel<<<dim3(NCH, Bb), 256>>>(out);
}

// round 6
// speedup vs baseline: 3.0085x; 1.5046x over previous
#include <cuda_runtime.h>
#include <cuda_fp16.h>
#include <cstdint>

// ---------------- problem constants ----------------
#define Bb 8
#define Tt 4096
#define Pp 256
#define Mm 32768
#define Kx 512            // K (single-term fp16: error budget allows it)
#define Nn 768            // angles 256 + inj 512
#define TILE_M 128
#define TILE_N 128
#define KC 64             // k-chunk (64 fp16 = 128B rows)
#define NCHUNK (Kx / KC)  // 8
#define NSTAGES 3
#define A_BYTES (TILE_M * 128)          // 16384
#define B_BYTES (TILE_N * 128)          // 16384
#define STAGE_BYTES (A_BYTES + B_BYTES) // 32768
#define DYN_BYTES (NSTAGES * STAGE_BYTES)   // 98304 -> 2 CTAs/SM

// scan chunking
#define SCHUNK 32
#define NCH (Tt / SCHUNK)         // 128

// ---------------- device scratch (no allocation) ----------------
__device__ __half  g_Ah[(size_t)Mm * Kx];
__device__ __half  g_Bh[(size_t)Nn * Kx];
__device__ float   g_bcat[Nn];
__device__ float   g_ang[(size_t)Mm * Pp];     // raw angles (theta)
__device__ float   g_dec[Mm];
__device__ float4  g_agg[(size_t)Bb * NCH * Pp];
__device__ float2  g_hst[(size_t)Bb * NCH * Pp];

// ---------------- helpers ----------------
__device__ __forceinline__ uint32_t smem_u32(const void* p) {
    uint32_t a;
    asm("{ .reg .u64 t; cvta.to.shared.u64 t, %1; cvt.u32.u64 %0, t; }" : "=r"(a) : "l"(p));
    return a;
}
#define SWZ(off) ((off) ^ (((off) >> 3) & 0x70))

#define CP_ASYNC16(dst, src) \
    asm volatile("cp.async.cg.shared.global [%0], [%1], 16;" :: "r"(dst), "l"(src))
#define CP_COMMIT() asm volatile("cp.async.commit_group;" ::: "memory")
#define CP_WAIT(n)  asm volatile("cp.async.wait_group %0;" :: "n"(n) : "memory")

__device__ __forceinline__ void ldsm_x4(uint32_t* r, uint32_t addr) {
    asm volatile("ldmatrix.sync.aligned.m8n8.x4.shared.b16 {%0,%1,%2,%3}, [%4];"
                 : "=r"(r[0]), "=r"(r[1]), "=r"(r[2]), "=r"(r[3]) : "r"(addr));
}

#define MMA_F16(C, A, B0, B1)                                                    \
    asm volatile("mma.sync.aligned.m16n8k16.row.col.f32.f16.f16.f32 "            \
                 "{%0,%1,%2,%3}, {%4,%5,%6,%7}, {%8,%9}, {%0,%1,%2,%3};\n"       \
                 : "+f"((C)[0]), "+f"((C)[1]), "+f"((C)[2]), "+f"((C)[3])        \
                 : "r"((A)[0]), "r"((A)[1]), "r"((A)[2]), "r"((A)[3]),           \
                   "r"(B0), "r"(B1))

// ---------------- fast sincos (FMA pipe, no MUFU) ----------------
__device__ __forceinline__ void fsincos(float a, float& s, float& c) {
    float n = rintf(a * 0.6366197723675814f);
    int q = (int)n;
    float r = fmaf(n, -1.5707963705062866f, a);
    r = fmaf(n, 4.3711388e-8f, r);
    float r2 = r * r;
    float sp = r * fmaf(r2, fmaf(r2, fmaf(r2, -1.9841270e-4f, 8.3333338e-3f),
                                  -1.6666667e-1f), 1.0f);
    float cp = fmaf(r2, fmaf(r2, fmaf(r2, -1.3888889e-3f, 4.1666668e-2f), -0.5f), 1.0f);
    bool swap = q & 1;
    float ss = swap ? cp : sp;
    float cc = swap ? sp : cp;
    if (q & 2) ss = -ss;
    if ((q + 1) & 2) cc = -cc;
    s = ss; c = cc;
}

// ---------------- prep: Wh fp16 transposed [n][k], bias ----------------
__global__ void prep_kernel(const float* __restrict__ Wa, const float* __restrict__ ba,
                            const float* __restrict__ Wi, const float* __restrict__ bi) {
    int n = blockIdx.y;
    int k = blockIdx.x * 256 + threadIdx.x;   // 0..511
    float w = (n < 256) ? Wa[k * 256 + n] : Wi[k * 512 + (n - 256)];
    g_Bh[(size_t)n * Kx + k] = __float2half_rn(w);
    if (blockIdx.x == 0 && threadIdx.x == 0)
        g_bcat[n] = (n < 256) ? ba[n] : bi[n - 256];
}

// ---------------- conv: X -> fp16, fused decay GEMV ----------------
__global__ __launch_bounds__(256) void conv_kernel(const float* __restrict__ X,
                                                   const float* __restrict__ Wd,
                                                   const float* __restrict__ bd) {
    int wid = threadIdx.x >> 5, lane = threadIdx.x & 31;
    size_t row = (size_t)blockIdx.x * 8 + wid;
    const float4* xp = (const float4*)(X + row * Kx);
    const float4* wp = (const float4*)Wd;
    float acc = 0.f;
    #pragma unroll
    for (int j = 0; j < 4; j++) {
        int idx = j * 32 + lane;
        float4 v = xp[idx];
        float4 w = wp[idx];
        acc = fmaf(v.x, w.x, fmaf(v.y, w.y, fmaf(v.z, w.z, fmaf(v.w, w.w, acc))));
        __half2 H0 = __floats2half2_rn(v.x, v.y);
        __half2 H1 = __floats2half2_rn(v.z, v.w);
        uint2 hp;
        hp.x = *(uint32_t*)&H0; hp.y = *(uint32_t*)&H1;
        *(uint2*)(g_Ah + row * Kx + idx * 4) = hp;
    }
    #pragma unroll
    for (int o = 16; o; o >>= 1) acc += __shfl_xor_sync(0xffffffffu, acc, o);
    if (!lane) g_dec[row] = 1.f / (1.f + __expf(-(acc + bd[0])));
}

// ---------------- GEMM: fp16 mma.sync, 3-stage cp.async, 2 CTAs/SM ----------------
// C[32768,768] = xh[32768,512] @ Wh[768,512]^T ; angles -> g_ang, inj -> out.
__global__ __launch_bounds__(256, 2) void gemm_kernel(float* __restrict__ out) {
    extern __shared__ char dyn[];
    const uint32_t dbase = smem_u32(dyn);
    __shared__ float s_bias[TILE_N];

    const int tid  = threadIdx.x;
    const int warp = tid >> 5;
    const int lane = tid & 31;
    const int g    = lane >> 2;
    const int q    = lane & 3;
    const int m0   = blockIdx.y * TILE_M;
    const int n0   = blockIdx.x * TILE_N;
    const int wm   = (warp & 1) * 64;
    const int wn   = (warp >> 1) * 32;

    if (tid < TILE_N) s_bias[tid] = g_bcat[n0 + tid];

    const int arow = tid >> 3;
    const int aj   = tid & 7;

    auto issue = [&](int c) {
        const int s = c % NSTAGES;
        const int xk0 = c * KC;
        uint32_t stA = dbase + s * STAGE_BYTES;
        uint32_t stB = stA + A_BYTES;
        #pragma unroll
        for (int i = 0; i < 4; i++) {
            int row = arow + i * 32;
            uint32_t off = SWZ((uint32_t)(row * 128 + aj * 16));
            CP_ASYNC16(stA + off, (const char*)(g_Ah + (size_t)(m0 + row) * Kx + xk0) + aj * 16);
            CP_ASYNC16(stB + off, (const char*)(g_Bh + (size_t)(n0 + row) * Kx + xk0) + aj * 16);
        }
    };

    float acc[4][4][4] = {};

    issue(0); CP_COMMIT();
    issue(1); CP_COMMIT();

    const int a_r  = lane & 15;
    const int a_kh = (lane >> 4) * 16;
    const int b_n  = lane & 15;
    const int b_kh = (lane >> 4) * 16;

    for (int c = 0; c < NCHUNK; ++c) {
        const int s = c % NSTAGES;
        CP_WAIT(1);
        __syncthreads();
        if (c + 2 < NCHUNK) issue(c + 2);
        CP_COMMIT();

        const uint32_t stA = dbase + s * STAGE_BYTES;
        const uint32_t stB = stA + A_BYTES;

        #pragma unroll
        for (int ks = 0; ks < 4; ks++) {
            uint32_t bf[4][2];
            #pragma unroll
            for (int h = 0; h < 2; h++) {
                uint32_t r[4];
                uint32_t off = (uint32_t)((wn + h * 16 + b_n) * 128 + ks * 32 + b_kh);
                ldsm_x4(r, stB + SWZ(off));
                bf[h * 2 + 0][0] = r[0]; bf[h * 2 + 0][1] = r[2];
                bf[h * 2 + 1][0] = r[1]; bf[h * 2 + 1][1] = r[3];
            }
            #pragma unroll
            for (int mi = 0; mi < 4; mi++) {
                uint32_t af[4];
                uint32_t off = (uint32_t)((wm + mi * 16 + a_r) * 128 + ks * 32 + a_kh);
                ldsm_x4(af, stA + SWZ(off));
                #pragma unroll
                for (int ni = 0; ni < 4; ni++)
                    MMA_F16(acc[mi][ni], af, bf[ni][0], bf[ni][1]);
            }
        }
    }

    const bool is_angle = (n0 < 256);
    #pragma unroll
    for (int mi = 0; mi < 4; mi++) {
        const int r0 = m0 + wm + mi * 16 + g;
        #pragma unroll
        for (int ni = 0; ni < 4; ni++) {
            const int col = wn + ni * 8 + 2 * q;
            const float b0 = s_bias[col], b1 = s_bias[col + 1];
            float v0 = acc[mi][ni][0] + b0;
            float v1 = acc[mi][ni][1] + b1;
            float v2 = acc[mi][ni][2] + b0;
            float v3 = acc[mi][ni][3] + b1;
            if (is_angle) {
                const int pc = n0 + col;
                *(float2*)(&g_ang[(size_t)r0 * 256 + pc])       = make_float2(v0, v1);
                *(float2*)(&g_ang[(size_t)(r0 + 8) * 256 + pc]) = make_float2(v2, v3);
            } else {
                const int e = n0 - 256 + col;
                *(float2*)(out + (size_t)r0 * 512 + e)       = make_float2(v0, v1);
                *(float2*)(out + (size_t)(r0 + 8) * 512 + e) = make_float2(v2, v3);
            }
        }
    }
}

// ---------------- parallel scan (3 passes), sincos recomputed from theta ----------------
__global__ __launch_bounds__(256) void scanA_kernel(const float* __restrict__ out) {
    const int p     = threadIdx.x;
    const int chunk = blockIdx.x;
    const int b     = blockIdx.y;
    const int t0    = chunk * SCHUNK;

    __shared__ float sd[SCHUNK];
    if (p < SCHUNK) sd[p] = g_dec[b * Tt + t0 + p];
    __syncthreads();

    const float*  ap = g_ang + ((size_t)b * Tt + t0) * Pp + p;
    const float2* up = (const float2*)out + ((size_t)b * Tt + t0) * Pp + p;

    float Zr = 1.f, Zi = 0.f, hr = 0.f, hi = 0.f;
    #pragma unroll 4
    for (int j = 0; j < SCHUNK; j++) {
        float th = ap[(size_t)j * Pp];
        float2 u = up[(size_t)j * Pp];
        float d = sd[j];
        float sv, cv;
        fsincos(th, sv, cv);
        float zr = d * cv, zi = d * sv;
        float nhr = fmaf(zr, hr, fmaf(-zi, hi, u.x));
        float nhi = fmaf(zr, hi, fmaf( zi, hr, u.y));
        hr = nhr; hi = nhi;
        float nZr = zr * Zr - zi * Zi;
        float nZi = fmaf(zr, Zi, zi * Zr);
        Zr = nZr; Zi = nZi;
    }
    g_agg[((size_t)b * NCH + chunk) * Pp + p] = make_float4(Zr, Zi, hr, hi);
}

__global__ __launch_bounds__(256) void scanB_kernel() {
    const int gid = blockIdx.x * 256 + threadIdx.x;
    const int b = gid >> 8, p = gid & 255;
    float hr = 0.f, hi = 0.f;
    for (int c = 0; c < NCH; c++) {
        const size_t idx = ((size_t)b * NCH + c) * Pp + p;
        float4 a = g_agg[idx];
        g_hst[idx] = make_float2(hr, hi);
        float nhr = fmaf(a.x, hr, fmaf(-a.y, hi, a.z));
        float nhi = fmaf(a.x, hi, fmaf( a.y, hr, a.w));
        hr = nhr; hi = nhi;
    }
}

__global__ __launch_bounds__(256) void scanC_kernel(float* __restrict__ out) {
    const int p     = threadIdx.x;
    const int chunk = blockIdx.x;
    const int b     = blockIdx.y;
    const int t0    = chunk * SCHUNK;

    __shared__ float sd[SCHUNK];
    if (p < SCHUNK) sd[p] = g_dec[b * Tt + t0 + p];
    __syncthreads();

    const float* ap = g_ang + ((size_t)b * Tt + t0) * Pp + p;
    float2*      op = (float2*)out + ((size_t)b * Tt + t0) * Pp + p;

    float2 h0 = g_hst[((size_t)b * NCH + chunk) * Pp + p];
    float hr = h0.x, hi = h0.y;
    #pragma unroll 4
    for (int j = 0; j < SCHUNK; j++) {
        float th = ap[(size_t)j * Pp];
        float2 u = op[(size_t)j * Pp];
        float d = sd[j];
        float sv, cv;
        fsincos(th, sv, cv);
        float zr = d * cv, zi = d * sv;
        float nhr = fmaf(zr, hr, fmaf(-zi, hi, u.x));
        float nhi = fmaf(zr, hi, fmaf( zi, hr, u.y));
        hr = nhr; hi = nhi;
        op[(size_t)j * Pp] = make_float2(hr, hi);
    }
}

// ---------------- launch ----------------
extern "C" void kernel_launch(void* const* d_in, const int* in_sizes, int n_in,
                              void* d_out, int out_size) {
    const float* x  = (const float*)d_in[0];
    const float* Wa = (const float*)d_in[1];
    const float* ba = (const float*)d_in[2];
    const float* Wd = (const float*)d_in[3];
    const float* bd = (const float*)d_in[4];
    const float* Wi = (const float*)d_in[5];
    const float* bi = (const float*)d_in[6];
    float* out = (float*)d_out;

    cudaFuncSetAttribute(gemm_kernel, cudaFuncAttributeMaxDynamicSharedMemorySize, DYN_BYTES);

    prep_kernel<<<dim3(Kx / 256, Nn), 256>>>(Wa, ba, Wi, bi);
    conv_kernel<<<Mm / 8, 256>>>(x, Wd, bd);
    gemm_kernel<<<dim3(Nn / TILE_N, Mm / TILE_M), 256, DYN_BYTES>>>(out);
    scanA_kernel<<<dim3(NCH, Bb), 256>>>(out);
    scanB_kernel<<<Bb, 256>>>();
    scanC_kernel<<<dim3(NCH, Bb), 256>>>(out);
}

// round 7
// speedup vs baseline: 3.2516x; 1.0808x over previous
#include <cuda_runtime.h>
#include <cuda_fp16.h>
#include <cstdint>

// ---------------- problem constants ----------------
#define Bb 8
#define Tt 4096
#define Pp 256
#define Mm 32768
#define Kx 512
#define Nn 768            // angles 256 + inj 512
#define TILE_M 128
#define TILE_N 128
#define KC 64             // k-chunk (64 fp16 = 128B rows)
#define NCHUNK (Kx / KC)  // 8
#define NSTAGES 3
#define A_BYTES (TILE_M * 128)
#define B_BYTES (TILE_N * 128)
#define STAGE_BYTES (A_BYTES + B_BYTES)
#define DYN_BYTES (NSTAGES * STAGE_BYTES)   // 98304 -> 2 CTAs/SM

// scan chunking
#define SCHUNK 32
#define NCH (Tt / SCHUNK)         // 128

// ---------------- device scratch (no allocation) ----------------
__device__ __half   g_Ah[(size_t)Mm * Kx];
__device__ __half   g_Bh[(size_t)Nn * Kx];
__device__ float    g_bcat[Nn];
__device__ float    g_ang[(size_t)Mm * Pp];     // raw angles (theta), fp32
__device__ __half2  g_u[(size_t)Mm * Pp];       // inj pairs, fp16
__device__ float    g_dec[Mm];
__device__ float4   g_agg[(size_t)Bb * NCH * Pp];
__device__ float2   g_hst[(size_t)Bb * NCH * Pp];

// ---------------- helpers ----------------
__device__ __forceinline__ uint32_t smem_u32(const void* p) {
    uint32_t a;
    asm("{ .reg .u64 t; cvta.to.shared.u64 t, %1; cvt.u32.u64 %0, t; }" : "=r"(a) : "l"(p));
    return a;
}
#define SWZ(off) ((off) ^ (((off) >> 3) & 0x70))

#define CP_ASYNC16(dst, src) \
    asm volatile("cp.async.cg.shared.global [%0], [%1], 16;" :: "r"(dst), "l"(src))
#define CP_COMMIT() asm volatile("cp.async.commit_group;" ::: "memory")
#define CP_WAIT(n)  asm volatile("cp.async.wait_group %0;" :: "n"(n) : "memory")

__device__ __forceinline__ void ldsm_x4(uint32_t* r, uint32_t addr) {
    asm volatile("ldmatrix.sync.aligned.m8n8.x4.shared.b16 {%0,%1,%2,%3}, [%4];"
                 : "=r"(r[0]), "=r"(r[1]), "=r"(r[2]), "=r"(r[3]) : "r"(addr));
}

#define MMA_F16(C, A, B0, B1)                                                    \
    asm volatile("mma.sync.aligned.m16n8k16.row.col.f32.f16.f16.f32 "            \
                 "{%0,%1,%2,%3}, {%4,%5,%6,%7}, {%8,%9}, {%0,%1,%2,%3};\n"       \
                 : "+f"((C)[0]), "+f"((C)[1]), "+f"((C)[2]), "+f"((C)[3])        \
                 : "r"((A)[0]), "r"((A)[1]), "r"((A)[2]), "r"((A)[3]),           \
                   "r"(B0), "r"(B1))

// ---------------- fast sincos (FMA pipe, no MUFU) ----------------
__device__ __forceinline__ void fsincos(float a, float& s, float& c) {
    float n = rintf(a * 0.6366197723675814f);
    int q = (int)n;
    float r = fmaf(n, -1.5707963705062866f, a);
    r = fmaf(n, 4.3711388e-8f, r);
    float r2 = r * r;
    float sp = r * fmaf(r2, fmaf(r2, fmaf(r2, -1.9841270e-4f, 8.3333338e-3f),
                                  -1.6666667e-1f), 1.0f);
    float cp = fmaf(r2, fmaf(r2, fmaf(r2, -1.3888889e-3f, 4.1666668e-2f), -0.5f), 1.0f);
    bool swap = q & 1;
    float ss = swap ? cp : sp;
    float cc = swap ? sp : cp;
    if (q & 2) ss = -ss;
    if ((q + 1) & 2) cc = -cc;
    s = ss; c = cc;
}

// ---------------- prep: Wh fp16 transposed [n][k], bias ----------------
__global__ void prep_kernel(const float* __restrict__ Wa, const float* __restrict__ ba,
                            const float* __restrict__ Wi, const float* __restrict__ bi) {
    int n = blockIdx.y;
    int k = blockIdx.x * 256 + threadIdx.x;
    float w = (n < 256) ? Wa[k * 256 + n] : Wi[k * 512 + (n - 256)];
    g_Bh[(size_t)n * Kx + k] = __float2half_rn(w);
    if (blockIdx.x == 0 && threadIdx.x == 0)
        g_bcat[n] = (n < 256) ? ba[n] : bi[n - 256];
}

// ---------------- conv: X -> fp16, fused decay GEMV ----------------
__global__ __launch_bounds__(256) void conv_kernel(const float* __restrict__ X,
                                                   const float* __restrict__ Wd,
                                                   const float* __restrict__ bd) {
    int wid = threadIdx.x >> 5, lane = threadIdx.x & 31;
    size_t row = (size_t)blockIdx.x * 8 + wid;
    const float4* xp = (const float4*)(X + row * Kx);
    const float4* wp = (const float4*)Wd;
    float acc = 0.f;
    #pragma unroll
    for (int j = 0; j < 4; j++) {
        int idx = j * 32 + lane;
        float4 v = xp[idx];
        float4 w = wp[idx];
        acc = fmaf(v.x, w.x, fmaf(v.y, w.y, fmaf(v.z, w.z, fmaf(v.w, w.w, acc))));
        __half2 H0 = __floats2half2_rn(v.x, v.y);
        __half2 H1 = __floats2half2_rn(v.z, v.w);
        uint2 hp;
        hp.x = *(uint32_t*)&H0; hp.y = *(uint32_t*)&H1;
        *(uint2*)(g_Ah + row * Kx + idx * 4) = hp;
    }
    #pragma unroll
    for (int o = 16; o; o >>= 1) acc += __shfl_xor_sync(0xffffffffu, acc, o);
    if (!lane) g_dec[row] = 1.f / (1.f + __expf(-(acc + bd[0])));
}

// ---------------- GEMM: fp16 mma.sync, 3-stage cp.async, 2 CTAs/SM ----------------
__global__ __launch_bounds__(256, 2) void gemm_kernel() {
    extern __shared__ char dyn[];
    const uint32_t dbase = smem_u32(dyn);
    __shared__ float s_bias[TILE_N];

    const int tid  = threadIdx.x;
    const int warp = tid >> 5;
    const int lane = tid & 31;
    const int g    = lane >> 2;
    const int q    = lane & 3;
    const int m0   = blockIdx.y * TILE_M;
    const int n0   = blockIdx.x * TILE_N;
    const int wm   = (warp & 1) * 64;
    const int wn   = (warp >> 1) * 32;

    if (tid < TILE_N) s_bias[tid] = g_bcat[n0 + tid];

    const int arow = tid >> 3;
    const int aj   = tid & 7;

    auto issue = [&](int c) {
        const int s = c % NSTAGES;
        const int xk0 = c * KC;
        uint32_t stA = dbase + s * STAGE_BYTES;
        uint32_t stB = stA + A_BYTES;
        #pragma unroll
        for (int i = 0; i < 4; i++) {
            int row = arow + i * 32;
            uint32_t off = SWZ((uint32_t)(row * 128 + aj * 16));
            CP_ASYNC16(stA + off, (const char*)(g_Ah + (size_t)(m0 + row) * Kx + xk0) + aj * 16);
            CP_ASYNC16(stB + off, (const char*)(g_Bh + (size_t)(n0 + row) * Kx + xk0) + aj * 16);
        }
    };

    float acc[4][4][4] = {};

    issue(0); CP_COMMIT();
    issue(1); CP_COMMIT();

    const int a_r  = lane & 15;
    const int a_kh = (lane >> 4) * 16;
    const int b_n  = lane & 15;
    const int b_kh = (lane >> 4) * 16;

    for (int c = 0; c < NCHUNK; ++c) {
        const int s = c % NSTAGES;
        CP_WAIT(1);
        __syncthreads();
        if (c + 2 < NCHUNK) issue(c + 2);
        CP_COMMIT();

        const uint32_t stA = dbase + s * STAGE_BYTES;
        const uint32_t stB = stA + A_BYTES;

        #pragma unroll
        for (int ks = 0; ks < 4; ks++) {
            uint32_t bf[4][2];
            #pragma unroll
            for (int h = 0; h < 2; h++) {
                uint32_t r[4];
                uint32_t off = (uint32_t)((wn + h * 16 + b_n) * 128 + ks * 32 + b_kh);
                ldsm_x4(r, stB + SWZ(off));
                bf[h * 2 + 0][0] = r[0]; bf[h * 2 + 0][1] = r[2];
                bf[h * 2 + 1][0] = r[1]; bf[h * 2 + 1][1] = r[3];
            }
            #pragma unroll
            for (int mi = 0; mi < 4; mi++) {
                uint32_t af[4];
                uint32_t off = (uint32_t)((wm + mi * 16 + a_r) * 128 + ks * 32 + a_kh);
                ldsm_x4(af, stA + SWZ(off));
                #pragma unroll
                for (int ni = 0; ni < 4; ni++)
                    MMA_F16(acc[mi][ni], af, bf[ni][0], bf[ni][1]);
            }
        }
    }

    const bool is_angle = (n0 < 256);
    #pragma unroll
    for (int mi = 0; mi < 4; mi++) {
        const int r0 = m0 + wm + mi * 16 + g;
        #pragma unroll
        for (int ni = 0; ni < 4; ni++) {
            const int col = wn + ni * 8 + 2 * q;
            const float b0 = s_bias[col], b1 = s_bias[col + 1];
            float v0 = acc[mi][ni][0] + b0;
            float v1 = acc[mi][ni][1] + b1;
            float v2 = acc[mi][ni][2] + b0;
            float v3 = acc[mi][ni][3] + b1;
            if (is_angle) {
                const int pc = n0 + col;
                *(float2*)(&g_ang[(size_t)r0 * 256 + pc])       = make_float2(v0, v1);
                *(float2*)(&g_ang[(size_t)(r0 + 8) * 256 + pc]) = make_float2(v2, v3);
            } else {
                const int pu = (n0 - 256 + col) >> 1;     // pair index
                g_u[(size_t)r0 * Pp + pu]       = __floats2half2_rn(v0, v1);
                g_u[(size_t)(r0 + 8) * Pp + pu] = __floats2half2_rn(v2, v3);
            }
        }
    }
}

// ---------------- parallel scan (3 passes) ----------------
__global__ __launch_bounds__(256) void scanA_kernel() {
    const int p     = threadIdx.x;
    const int chunk = blockIdx.x;
    const int b     = blockIdx.y;
    const int t0    = chunk * SCHUNK;

    __shared__ float sd[SCHUNK];
    if (p < SCHUNK) sd[p] = g_dec[b * Tt + t0 + p];
    __syncthreads();

    const float*   ap = g_ang + ((size_t)b * Tt + t0) * Pp + p;
    const __half2* up = g_u   + ((size_t)b * Tt + t0) * Pp + p;

    float Zr = 1.f, Zi = 0.f, hr = 0.f, hi = 0.f;
    #pragma unroll 4
    for (int j = 0; j < SCHUNK; j++) {
        float th = ap[(size_t)j * Pp];
        float2 u = __half22float2(up[(size_t)j * Pp]);
        float d = sd[j];
        float sv, cv;
        fsincos(th, sv, cv);
        float zr = d * cv, zi = d * sv;
        float nhr = fmaf(zr, hr, fmaf(-zi, hi, u.x));
        float nhi = fmaf(zr, hi, fmaf( zi, hr, u.y));
        hr = nhr; hi = nhi;
        float nZr = zr * Zr - zi * Zi;
        float nZi = fmaf(zr, Zi, zi * Zr);
        Zr = nZr; Zi = nZi;
    }
    g_agg[((size_t)b * NCH + chunk) * Pp + p] = make_float4(Zr, Zi, hr, hi);
}

// unroll-8 batched prefetch: MLP 8 instead of ~1
__global__ __launch_bounds__(256) void scanB_kernel() {
    const int gid = blockIdx.x * 256 + threadIdx.x;
    const int b = gid >> 8, p = gid & 255;
    const size_t base = (size_t)b * NCH * Pp + p;
    float hr = 0.f, hi = 0.f;
    for (int c0 = 0; c0 < NCH; c0 += 8) {
        float4 a[8];
        #pragma unroll
        for (int i = 0; i < 8; i++) a[i] = g_agg[base + (size_t)(c0 + i) * Pp];
        #pragma unroll
        for (int i = 0; i < 8; i++) {
            g_hst[base + (size_t)(c0 + i) * Pp] = make_float2(hr, hi);
            float nhr = fmaf(a[i].x, hr, fmaf(-a[i].y, hi, a[i].z));
            float nhi = fmaf(a[i].x, hi, fmaf( a[i].y, hr, a[i].w));
            hr = nhr; hi = nhi;
        }
    }
}

__global__ __launch_bounds__(256) void scanC_kernel(float* __restrict__ out) {
    const int p     = threadIdx.x;
    const int chunk = blockIdx.x;
    const int b     = blockIdx.y;
    const int t0    = chunk * SCHUNK;

    __shared__ float sd[SCHUNK];
    if (p < SCHUNK) sd[p] = g_dec[b * Tt + t0 + p];
    __syncthreads();

    const float*   ap = g_ang + ((size_t)b * Tt + t0) * Pp + p;
    const __half2* up = g_u   + ((size_t)b * Tt + t0) * Pp + p;
    float2*        op = (float2*)out + ((size_t)b * Tt + t0) * Pp + p;

    float2 h0 = g_hst[((size_t)b * NCH + chunk) * Pp + p];
    float hr = h0.x, hi = h0.y;
    #pragma unroll 4
    for (int j = 0; j < SCHUNK; j++) {
        float th = ap[(size_t)j * Pp];
        float2 u = __half22float2(up[(size_t)j * Pp]);
        float d = sd[j];
        float sv, cv;
        fsincos(th, sv, cv);
        float zr = d * cv, zi = d * sv;
        float nhr = fmaf(zr, hr, fmaf(-zi, hi, u.x));
        float nhi = fmaf(zr, hi, fmaf( zi, hr, u.y));
        hr = nhr; hi = nhi;
        op[(size_t)j * Pp] = make_float2(hr, hi);
    }
}

// ---------------- launch ----------------
extern "C" void kernel_launch(void* const* d_in, const int* in_sizes, int n_in,
                              void* d_out, int out_size) {
    const float* x  = (const float*)d_in[0];
    const float* Wa = (const float*)d_in[1];
    const float* ba = (const float*)d_in[2];
    const float* Wd = (const float*)d_in[3];
    const float* bd = (const float*)d_in[4];
    const float* Wi = (const float*)d_in[5];
    const float* bi = (const float*)d_in[6];
    float* out = (float*)d_out;

    cudaFuncSetAttribute(gemm_kernel, cudaFuncAttributeMaxDynamicSharedMemorySize, DYN_BYTES);

    prep_kernel<<<dim3(Kx / 256, Nn), 256>>>(Wa, ba, Wi, bi);
    conv_kernel<<<Mm / 8, 256>>>(x, Wd, bd);
    gemm_kernel<<<dim3(Nn / TILE_N, Mm / TILE_M), 256, DYN_BYTES>>>();
    scanA_kernel<<<dim3(NCH, Bb), 256>>>();
    scanB_kernel<<<Bb, 256>>>();
    scanC_kernel<<<dim3(NCH, Bb), 256>>>(out);
}